// round 13
// baseline (speedup 1.0000x reference)
#include <cuda_runtime.h>
#include <cuda_fp16.h>
#include <cstdint>
#include <math.h>

// ---------------- problem constants ----------------
#define B_    32
#define N_    577
#define C_    768
#define H_    12
#define D_    64
#define GRID_ 24
#define RAD_  3
#define K_    768
#define M_    (B_*N_)      // 18464
#define MT_   145          // ceil(M/128)
#define MPAD_ (MT_*128)    // 18560

// ---------------- device-global scratch ----------------
__device__ __half  g_xhi[MPAD_*K_];
__device__ __half  g_xlo[MPAD_*K_];
__device__ __half  g_Whi[3*C_*K_];   // Wqkv^T  [2304,768] fp16
__device__ __half  g_Phi[C_*K_];     // Wproj^T [768,768]  fp16
__device__ __half  g_QKV[(size_t)M_*3*C_];      // [m, 2304] fp16
__device__ __half  g_Ohi[MPAD_*C_];
__device__ __half  g_Olo[MPAD_*C_];

// ---------------- PTX helpers ----------------
__device__ __forceinline__ uint32_t smem_u32(const void* p) {
    uint32_t a;
    asm("{ .reg .u64 t; cvta.to.shared.u64 t, %1; cvt.u32.u64 %0, t; }" : "=r"(a) : "l"(p));
    return a;
}
__device__ __forceinline__ void cp_async16(uint32_t dst, const void* src) {
    asm volatile("cp.async.cg.shared.global [%0], [%1], 16;" :: "r"(dst), "l"(src));
}
__device__ __forceinline__ void cp_commit() {
    asm volatile("cp.async.commit_group;");
}
template <int NN>
__device__ __forceinline__ void cp_wait() {
    asm volatile("cp.async.wait_group %0;" :: "n"(NN));
}
__device__ __forceinline__ void ldmatrix_x4(uint32_t& r0, uint32_t& r1,
                                            uint32_t& r2, uint32_t& r3, uint32_t addr) {
    asm volatile("ldmatrix.sync.aligned.m8n8.x4.shared.b16 {%0,%1,%2,%3}, [%4];"
                 : "=r"(r0), "=r"(r1), "=r"(r2), "=r"(r3) : "r"(addr));
}
__device__ __forceinline__ void mma_fp16(float* c, const uint32_t* a,
                                         uint32_t b0, uint32_t b1) {
    asm volatile(
        "mma.sync.aligned.m16n8k16.row.col.f32.f16.f16.f32 "
        "{%0,%1,%2,%3}, {%4,%5,%6,%7}, {%8,%9}, {%0,%1,%2,%3};"
        : "+f"(c[0]), "+f"(c[1]), "+f"(c[2]), "+f"(c[3])
        : "r"(a[0]), "r"(a[1]), "r"(a[2]), "r"(a[3]), "r"(b0), "r"(b1));
}

// ============================================================================
// conversion kernels
// ============================================================================
__global__ void conv_x_kernel(const float* __restrict__ x) {
    size_t idx = (size_t)blockIdx.x * 256 + threadIdx.x;
    if (idx >= (size_t)MPAD_ * K_) return;
    size_t m = idx / K_;
    if (m < M_) {
        float a = x[idx];
        __half hi = __float2half(a);
        __half lo = __float2half(a - __half2float(hi));
        g_xhi[idx] = hi;
        g_xlo[idx] = lo;
    } else {
        g_xhi[idx] = __float2half(0.f);
        g_xlo[idx] = __float2half(0.f);
        g_Ohi[idx] = __float2half(0.f);
        g_Olo[idx] = __float2half(0.f);
    }
}

__global__ void conv_wT_kernel(const float* __restrict__ W,
                               __half* __restrict__ Thi, int Ncols) {
    __shared__ float t[32][33];
    const int kc = blockIdx.y * 32;
    const int nc = blockIdx.x * 32;
    const int tx = threadIdx.x & 31;
    const int ty = threadIdx.x >> 5;
    for (int i = ty; i < 32; i += 8)
        t[i][tx] = W[(size_t)(kc + i) * Ncols + nc + tx];
    __syncthreads();
    for (int i = ty; i < 32; i += 8) {
        size_t o = (size_t)(nc + i) * K_ + kc + tx;
        Thi[o] = __float2half(t[tx][i]);
    }
}

// ============================================================================
// fp16 2-term HMMA GEMM: C = (Ahi+Alo) @ Bhi^T (+bias)  (unchanged)
// ============================================================================
#define NCHUNK   (K_/64)
#define A_B      (128*128)
#define B_B      (64*128)
#define STAGE_B  (2*A_B + B_B)
#define GEMM_SMEM (2*STAGE_B)

template <int HALF_OUT>
__global__ __launch_bounds__(256, 2)
void hmma_gemm_kernel(const __half* __restrict__ Ahi,
                      const __half* __restrict__ Alo,
                      const __half* __restrict__ Bh,
                      const float* __restrict__ bias,
                      void* __restrict__ CoutV,
                      int Ncols, int Mrows)
{
    extern __shared__ unsigned char smem[];
    const uint32_t s_base = smem_u32(smem);

    const int tid   = threadIdx.x;
    const int wid   = tid >> 5;
    const int lane  = tid & 31;
    const int m0    = blockIdx.y * 128;
    const int n0    = blockIdx.x * 64;
    const int wm    = (wid >> 1) * 32;
    const int wn    = (wid & 1) * 32;

    const int lr = tid >> 3;
    const int lc = tid & 7;
    auto load_stage = [&](int st, int kc) {
        const uint32_t sb = s_base + st * STAGE_B;
        const int k0 = kc * 64 + lc * 8;
#pragma unroll
        for (int i = 0; i < 4; i++) {
            const int row = lr + i * 32;
            const uint32_t so = row * 128 + ((lc ^ (row & 7)) << 4);
            const size_t ga = (size_t)(m0 + row) * K_ + k0;
            cp_async16(sb + so,        Ahi + ga);
            cp_async16(sb + A_B + so,  Alo + ga);
        }
#pragma unroll
        for (int i = 0; i < 2; i++) {
            const int row = lr + i * 32;
            const uint32_t so = row * 128 + ((lc ^ (row & 7)) << 4);
            const size_t gb = (size_t)(n0 + row) * K_ + k0;
            cp_async16(sb + 2*A_B + so, Bh + gb);
        }
    };

    float acc[2][4][4];
#pragma unroll
    for (int i = 0; i < 2; i++)
#pragma unroll
        for (int j = 0; j < 4; j++)
#pragma unroll
            for (int v = 0; v < 4; v++) acc[i][j][v] = 0.f;

    load_stage(0, 0); cp_commit();

    const int a_row = (lane & 15);
    const int a_chi = (lane >> 4);
    const int b_row = (lane & 7) + ((lane >> 4) << 3);
    const int b_chi = (lane >> 3) & 1;

    for (int kc = 0; kc < NCHUNK; kc++) {
        if (kc + 1 < NCHUNK) {
            load_stage((kc + 1) & 1, kc + 1);
            cp_commit();
            cp_wait<1>();
        } else {
            cp_wait<0>();
        }
        __syncthreads();

        const uint32_t sb   = s_base + (kc & 1) * STAGE_B;
        const uint32_t sAhi = sb;
        const uint32_t sAlo = sb + A_B;
        const uint32_t sBh  = sb + 2*A_B;

#pragma unroll
        for (int s = 0; s < 4; s++) {
            uint32_t fah[2][4], fal[2][4];
#pragma unroll
            for (int mi = 0; mi < 2; mi++) {
                const int row = wm + mi * 16 + a_row;
                const int ch  = (2 * s + a_chi) ^ (row & 7);
                const uint32_t off = row * 128 + (ch << 4);
                ldmatrix_x4(fah[mi][0], fah[mi][1], fah[mi][2], fah[mi][3], sAhi + off);
                ldmatrix_x4(fal[mi][0], fal[mi][1], fal[mi][2], fal[mi][3], sAlo + off);
            }
            uint32_t fbh[2][4];
#pragma unroll
            for (int ng = 0; ng < 2; ng++) {
                const int row = wn + ng * 16 + b_row;
                const int ch  = (2 * s + b_chi) ^ (row & 7);
                const uint32_t off = row * 128 + (ch << 4);
                ldmatrix_x4(fbh[ng][0], fbh[ng][1], fbh[ng][2], fbh[ng][3], sBh + off);
            }
#pragma unroll
            for (int mi = 0; mi < 2; mi++) {
#pragma unroll
                for (int ng = 0; ng < 2; ng++) {
#pragma unroll
                    for (int hh = 0; hh < 2; hh++) {
                        float* c = acc[mi][ng * 2 + hh];
                        const uint32_t b0 = fbh[ng][hh * 2], b1 = fbh[ng][hh * 2 + 1];
                        mma_fp16(c, fah[mi], b0, b1);
                        mma_fp16(c, fal[mi], b0, b1);
                    }
                }
            }
        }
        __syncthreads();
    }

#pragma unroll
    for (int ni = 0; ni < 4; ni++) {
        const int col = n0 + wn + ni * 8 + (lane & 3) * 2;
        if (HALF_OUT) {
            __half* Cout = (__half*)CoutV;
#pragma unroll
            for (int mi = 0; mi < 2; mi++) {
                const int r0 = m0 + wm + mi * 16 + (lane >> 2);
                if (r0 < Mrows) {
                    __half2 v; v.x = __float2half(acc[mi][ni][0]); v.y = __float2half(acc[mi][ni][1]);
                    *(__half2*)(Cout + (size_t)r0 * Ncols + col) = v;
                }
                const int r1 = r0 + 8;
                if (r1 < Mrows) {
                    __half2 v; v.x = __float2half(acc[mi][ni][2]); v.y = __float2half(acc[mi][ni][3]);
                    *(__half2*)(Cout + (size_t)r1 * Ncols + col) = v;
                }
            }
        } else {
            float* Cout = (float*)CoutV;
            const float bx = bias ? bias[col]     : 0.f;
            const float by = bias ? bias[col + 1] : 0.f;
#pragma unroll
            for (int mi = 0; mi < 2; mi++) {
                const int r0 = m0 + wm + mi * 16 + (lane >> 2);
                if (r0 < Mrows) {
                    float2 v = make_float2(acc[mi][ni][0] + bx, acc[mi][ni][1] + by);
                    *(float2*)(Cout + (size_t)r0 * Ncols + col) = v;
                }
                const int r1 = r0 + 8;
                if (r1 < Mrows) {
                    float2 v = make_float2(acc[mi][ni][2] + bx, acc[mi][ni][3] + by);
                    *(float2*)(Cout + (size_t)r1 * Ncols + col) = v;
                }
            }
        }
    }
}

// ============================================================================
// merged attention kernel — fused QK/softmax/AV per query, probs via shfl
//   blk <  B*H*GRID  : local-row CTA (smem: sQ + sK + sV only, ~50.5KB)
//   blk >= B*H*GRID  : CLS CTA for (b,h)
// ============================================================================
#define MAXNK     169
#define KSTRH     72                 // halves per K/V row (144B)
#define NLOCALBLK (B_*H_*GRID_)      // 9216
#define SQ_H      (24*64)            // 1536 halves (3072B)
#define SKV_H     (MAXNK*KSTRH)      // 12168 halves (24336B)
#define ATT_SMEM  (SQ_H*2 + 2*SKV_H*2)   // 51,744 B -> 4 CTAs/SM

__global__ __launch_bounds__(256, 4)
void attn_kernel()
{
    extern __shared__ unsigned char smraw[];

    const int tid  = threadIdx.x;
    const int lane = tid & 31;
    const int warp = tid >> 5;
    const int blk  = blockIdx.x;

    if (blk < NLOCALBLK) {
        __half* sQ  = (__half*)smraw;                       // [24][64]
        __half* sK  = sQ + SQ_H;                            // [169][72]
        __half* sV  = sK + SKV_H;                           // [169][72]
        const uint32_t aQ = smem_u32(sQ);
        const uint32_t aK = smem_u32(sK);
        const uint32_t aV = smem_u32(sV);

        const int r = blk % GRID_;
        const int h = (blk / GRID_) % H_;
        const int b = blk / (GRID_ * H_);

        const int r0   = (r - RAD_ < 0) ? 0 : r - RAD_;
        const int r1   = (r + RAD_ > GRID_ - 1) ? GRID_ - 1 : r + RAD_;
        const int span = r1 - r0 + 1;
        const int nk   = span * GRID_ + 1;

        const size_t krow0 = (size_t)b * N_ * (3 * C_);
        const int koff = C_ + h * D_;
        const int voff = 2 * C_ + h * D_;
        const size_t qbase = ((size_t)b * N_ + 1 + r * GRID_) * (3 * C_) + h * D_;

        // ---- single async fill: queries + K band + V band ----
        for (int i = tid; i < 24 * 8; i += 256) {
            const int c    = i >> 3;
            const int part = i & 7;
            cp_async16(aQ + (uint32_t)(c * 64 + part * 8) * 2,
                       g_QKV + qbase + (size_t)c * (3 * C_) + part * 8);
        }
        for (int i = tid; i < nk * 8; i += 256) {
            const int slot = i >> 3;
            const int part = i & 7;
            const int gkey = (slot == 0) ? 0
                           : (1 + (r0 + (slot - 1) / GRID_) * GRID_ + (slot - 1) % GRID_);
            const __half* gp = g_QKV + krow0 + (size_t)gkey * (3 * C_);
            const uint32_t so = (uint32_t)(slot * KSTRH + part * 8) * 2;
            cp_async16(aK + so, gp + koff + part * 8);
            cp_async16(aV + so, gp + voff + part * 8);
        }
        cp_commit();
        cp_wait<0>();
        __syncthreads();

        // ---- fused QK + softmax + AV per query ----
        for (int c = warp; c < GRID_; c += 8) {
            const int c0 = (c - RAD_ < 0) ? 0 : c - RAD_;
            const int c1 = (c + RAD_ > GRID_ - 1) ? GRID_ - 1 : c + RAD_;
            const int cw = c1 - c0 + 1;
            const int cnt = 1 + span * cw;

            // lane -> key slot for QK (row-major over band, CLS at index 0)
            int slot0 = 0, slot1 = 0;
            if (lane > 0 && lane < cnt) {
                const int j = lane - 1;
                slot0 = 1 + (j / cw) * GRID_ + (c0 + j % cw);
            }
            if (lane + 32 < cnt) {
                const int j = lane + 31;
                slot1 = 1 + (j / cw) * GRID_ + (c0 + j % cw);
            }
            const __half* qrow = sQ + c * 64;
            const __half* k0r  = sK + slot0 * KSTRH;
            const __half* k1r  = sK + slot1 * KSTRH;
            float acc0 = 0.f, acc1 = 0.f;
#pragma unroll
            for (int i = 0; i < 8; i++) {
                const uint4 qv = *(const uint4*)(qrow + i * 8);
                const uint4 k0 = *(const uint4*)(k0r + i * 8);
                const uint4 k1 = *(const uint4*)(k1r + i * 8);
                const __half2* qh = (const __half2*)&qv;
                const __half2* kh0 = (const __half2*)&k0;
                const __half2* kh1 = (const __half2*)&k1;
#pragma unroll
                for (int w = 0; w < 4; w++) {
                    const float2 qf = __half22float2(qh[w]);
                    const float2 f0 = __half22float2(kh0[w]);
                    const float2 f1 = __half22float2(kh1[w]);
                    acc0 = fmaf(qf.x, f0.x, acc0);
                    acc0 = fmaf(qf.y, f0.y, acc0);
                    acc1 = fmaf(qf.x, f1.x, acc1);
                    acc1 = fmaf(qf.y, f1.y, acc1);
                }
            }
            float s0 = (lane < cnt)      ? acc0 * 0.125f : -1e30f;
            float s1 = (lane + 32 < cnt) ? acc1 * 0.125f : -1e30f;

            float mx = fmaxf(s0, s1);
#pragma unroll
            for (int off = 16; off; off >>= 1)
                mx = fmaxf(mx, __shfl_xor_sync(0xffffffffu, mx, off));
            const float e0 = __expf(s0 - mx);
            const float e1 = __expf(s1 - mx);
            float sum = e0 + e1;
#pragma unroll
            for (int off = 16; off; off >>= 1)
                sum += __shfl_xor_sync(0xffffffffu, sum, off);
            const float inv = 1.0f / sum;
            const float p0 = e0 * inv;   // prob of key (lane-1), lane0 = CLS
            const float p1 = e1 * inv;   // prob of key (lane+31)

            // ---- AV: direct nested addressing, probs broadcast via shfl ----
            float a0, a1;
            {   // CLS key (idx 0 -> p0 of lane 0)
                const float p = __shfl_sync(0xffffffffu, p0, 0);
                const __half2 vh = *(const __half2*)(sV + 2 * lane);
                const float2 vf = __half22float2(vh);
                a0 = p * vf.x;
                a1 = p * vf.y;
            }
            int idx = 1;
            for (int rr = r0; rr <= r1; rr++) {
                const int rowb = 1 + (rr - r0) * GRID_;
#pragma unroll 4
                for (int cc = c0; cc <= c1; cc++) {
                    const float p = (idx < 32)
                        ? __shfl_sync(0xffffffffu, p0, idx)
                        : __shfl_sync(0xffffffffu, p1, idx - 32);
                    idx++;
                    const __half2 vh = *(const __half2*)(sV + (rowb + cc) * KSTRH + 2 * lane);
                    const float2 vf = __half22float2(vh);
                    a0 = fmaf(p, vf.x, a0);
                    a1 = fmaf(p, vf.y, a1);
                }
            }

            const int n = 1 + r * GRID_ + c;
            const size_t o = ((size_t)b * N_ + n) * C_ + h * D_ + 2 * lane;
            const __half h0 = __float2half(a0);
            const __half h1 = __float2half(a1);
            __half2 hp; hp.x = h0; hp.y = h1;
            __half2 lp;
            lp.x = __float2half(a0 - __half2float(h0));
            lp.y = __float2half(a1 - __half2float(h1));
            *(__half2*)(g_Ohi + o) = hp;
            *(__half2*)(g_Olo + o) = lp;
        }
    } else {
        // ---------------- CLS CTA ----------------
        float* sm     = (float*)smraw;
        float* scores = sm;                 // [577] (+pad)
        float* partA  = sm + 640;           // [8][64]
        float* red    = sm + 640 + 8 * 64;  // [8]

        const int w2 = blk - NLOCALBLK;
        const int b  = w2 / H_;
        const int h  = w2 % H_;

        const size_t rowm = (size_t)b * N_;   // n = 0
        const __half* qp = g_QKV + rowm * (3 * C_) + h * D_;
        const float q0 = __half2float(qp[lane]);
        const float q1 = __half2float(qp[lane + 32]);

        const size_t krow0 = (size_t)b * N_ * (3 * C_);
        const int koff = C_ + h * D_;
        const int voff = 2 * C_ + h * D_;

        for (int j = warp; j < N_; j += 8) {
            const __half* kp = g_QKV + krow0 + (size_t)j * (3 * C_) + koff;
            float s = q0 * __half2float(kp[lane]) + q1 * __half2float(kp[lane + 32]);
#pragma unroll
            for (int off = 16; off; off >>= 1)
                s += __shfl_xor_sync(0xffffffffu, s, off);
            if (lane == 0) scores[j] = s * 0.125f;
        }
        __syncthreads();

        float mx = -1e30f;
        for (int i = tid; i < N_; i += 256) mx = fmaxf(mx, scores[i]);
#pragma unroll
        for (int off = 16; off; off >>= 1)
            mx = fmaxf(mx, __shfl_xor_sync(0xffffffffu, mx, off));
        if (lane == 0) red[warp] = mx;
        __syncthreads();
        mx = red[0];
#pragma unroll
        for (int w = 1; w < 8; w++) mx = fmaxf(mx, red[w]);
        __syncthreads();

        float lsum = 0.f;
        for (int i = tid; i < N_; i += 256) {
            float e = __expf(scores[i] - mx);
            scores[i] = e;
            lsum += e;
        }
#pragma unroll
        for (int off = 16; off; off >>= 1)
            lsum += __shfl_xor_sync(0xffffffffu, lsum, off);
        if (lane == 0) red[warp] = lsum;
        __syncthreads();
        float sum = 0.f;
#pragma unroll
        for (int w = 0; w < 8; w++) sum += red[w];
        const float inv = 1.0f / sum;

        float a0 = 0.f, a1 = 0.f;
        for (int j = warp; j < N_; j += 8) {
            const float p = scores[j];
            const __half* vp = g_QKV + krow0 + (size_t)j * (3 * C_) + voff;
            a0 = fmaf(p, __half2float(vp[lane]),      a0);
            a1 = fmaf(p, __half2float(vp[lane + 32]), a1);
        }
        partA[warp * 64 + lane]      = a0;
        partA[warp * 64 + lane + 32] = a1;
        __syncthreads();

        if (warp == 0) {
            float t0 = 0.f, t1 = 0.f;
#pragma unroll
            for (int w = 0; w < 8; w++) {
                t0 += partA[w * 64 + lane];
                t1 += partA[w * 64 + lane + 32];
            }
            t0 *= inv; t1 *= inv;
            const size_t o = rowm * C_ + h * D_;
            const __half h0 = __float2half(t0);
            const __half h1 = __float2half(t1);
            g_Ohi[o + lane]      = h0;
            g_Olo[o + lane]      = __float2half(t0 - __half2float(h0));
            g_Ohi[o + lane + 32] = h1;
            g_Olo[o + lane + 32] = __float2half(t1 - __half2float(h1));
        }
    }
}

// ============================================================================
// launch
// ============================================================================
extern "C" void kernel_launch(void* const* d_in, const int* in_sizes, int n_in,
                              void* d_out, int out_size)
{
    const float* x     = (const float*)d_in[0];
    const float* Wqkv  = (const float*)d_in[1];
    const float* Wproj = (const float*)d_in[2];
    const float* bproj = (const float*)d_in[3];
    float* out = (float*)d_out;

    cudaFuncSetAttribute(hmma_gemm_kernel<0>,
                         cudaFuncAttributeMaxDynamicSharedMemorySize, GEMM_SMEM);
    cudaFuncSetAttribute(hmma_gemm_kernel<1>,
                         cudaFuncAttributeMaxDynamicSharedMemorySize, GEMM_SMEM);
    cudaFuncSetAttribute(attn_kernel,
                         cudaFuncAttributeMaxDynamicSharedMemorySize, ATT_SMEM);

    __half *xhi, *xlo, *whi, *phi, *ohi, *olo, *qkv;
    cudaGetSymbolAddress((void**)&xhi, g_xhi);
    cudaGetSymbolAddress((void**)&xlo, g_xlo);
    cudaGetSymbolAddress((void**)&whi, g_Whi);
    cudaGetSymbolAddress((void**)&phi, g_Phi);
    cudaGetSymbolAddress((void**)&ohi, g_Ohi);
    cudaGetSymbolAddress((void**)&olo, g_Olo);
    cudaGetSymbolAddress((void**)&qkv, g_QKV);

    // 0) conversions
    {
        size_t total = (size_t)MPAD_ * K_;
        conv_x_kernel<<<(unsigned)((total + 255) / 256), 256>>>(x);
        conv_wT_kernel<<<dim3(3 * C_ / 32, K_ / 32), 256>>>(Wqkv, whi, 3 * C_);
        conv_wT_kernel<<<dim3(C_ / 32, K_ / 32), 256>>>(Wproj, phi, C_);
    }

    // 1) QKV GEMM: [M,768] @ [2304,768]^T -> g_QKV (fp16)
    hmma_gemm_kernel<1><<<dim3(3 * C_ / 64, MT_), 256, GEMM_SMEM>>>(
        xhi, xlo, whi, nullptr, qkv, 3 * C_, M_);

    // 2) attention (local + CLS in one launch)
    attn_kernel<<<NLOCALBLK + B_ * H_, 256, ATT_SMEM>>>();

    // 3) proj GEMM: [M,768] @ [768,768]^T + bias -> out (fp32)
    hmma_gemm_kernel<0><<<dim3(C_ / 64, MT_), 256, GEMM_SMEM>>>(
        ohi, olo, phi, bproj, out, C_, M_);
}

// round 14
// speedup vs baseline: 1.0822x; 1.0822x over previous
#include <cuda_runtime.h>
#include <cuda_fp16.h>
#include <cstdint>
#include <math.h>

// ---------------- problem constants ----------------
#define B_    32
#define N_    577
#define C_    768
#define H_    12
#define D_    64
#define GRID_ 24
#define RAD_  3
#define K_    768
#define M_    (B_*N_)      // 18464
#define MTG_  193          // ceil(M/96) gemm m-tiles
#define MPAD_ 18560        // padded rows (>= 193*96 = 18528)

// ---------------- device-global scratch ----------------
__device__ __half  g_xhi[MPAD_*K_];
__device__ __half  g_xlo[MPAD_*K_];
__device__ __half  g_Whi[3*C_*K_];   // Wqkv^T  [2304,768] fp16
__device__ __half  g_Phi[C_*K_];     // Wproj^T [768,768]  fp16
__device__ __half  g_QKV[(size_t)M_*3*C_];      // [m, 2304] fp16
__device__ __half  g_Ohi[MPAD_*C_];
__device__ __half  g_Olo[MPAD_*C_];

// ---------------- PTX helpers ----------------
__device__ __forceinline__ uint32_t smem_u32(const void* p) {
    uint32_t a;
    asm("{ .reg .u64 t; cvta.to.shared.u64 t, %1; cvt.u32.u64 %0, t; }" : "=r"(a) : "l"(p));
    return a;
}
__device__ __forceinline__ void cp_async16(uint32_t dst, const void* src) {
    asm volatile("cp.async.cg.shared.global [%0], [%1], 16;" :: "r"(dst), "l"(src));
}
__device__ __forceinline__ void cp_commit() {
    asm volatile("cp.async.commit_group;");
}
template <int NN>
__device__ __forceinline__ void cp_wait() {
    asm volatile("cp.async.wait_group %0;" :: "n"(NN));
}
__device__ __forceinline__ void ldmatrix_x4(uint32_t& r0, uint32_t& r1,
                                            uint32_t& r2, uint32_t& r3, uint32_t addr) {
    asm volatile("ldmatrix.sync.aligned.m8n8.x4.shared.b16 {%0,%1,%2,%3}, [%4];"
                 : "=r"(r0), "=r"(r1), "=r"(r2), "=r"(r3) : "r"(addr));
}
__device__ __forceinline__ void mma_fp16(float* c, const uint32_t* a,
                                         uint32_t b0, uint32_t b1) {
    asm volatile(
        "mma.sync.aligned.m16n8k16.row.col.f32.f16.f16.f32 "
        "{%0,%1,%2,%3}, {%4,%5,%6,%7}, {%8,%9}, {%0,%1,%2,%3};"
        : "+f"(c[0]), "+f"(c[1]), "+f"(c[2]), "+f"(c[3])
        : "r"(a[0]), "r"(a[1]), "r"(a[2]), "r"(a[3]), "r"(b0), "r"(b1));
}

// ============================================================================
// conversion kernels
// ============================================================================
__global__ void conv_x_kernel(const float* __restrict__ x) {
    size_t idx = (size_t)blockIdx.x * 256 + threadIdx.x;
    if (idx >= (size_t)MPAD_ * K_) return;
    size_t m = idx / K_;
    if (m < M_) {
        float a = x[idx];
        __half hi = __float2half(a);
        __half lo = __float2half(a - __half2float(hi));
        g_xhi[idx] = hi;
        g_xlo[idx] = lo;
    } else {
        g_xhi[idx] = __float2half(0.f);
        g_xlo[idx] = __float2half(0.f);
        g_Ohi[idx] = __float2half(0.f);
        g_Olo[idx] = __float2half(0.f);
    }
}

__global__ void conv_wT_kernel(const float* __restrict__ W,
                               __half* __restrict__ Thi, int Ncols) {
    __shared__ float t[32][33];
    const int kc = blockIdx.y * 32;
    const int nc = blockIdx.x * 32;
    const int tx = threadIdx.x & 31;
    const int ty = threadIdx.x >> 5;
    for (int i = ty; i < 32; i += 8)
        t[i][tx] = W[(size_t)(kc + i) * Ncols + nc + tx];
    __syncthreads();
    for (int i = ty; i < 32; i += 8) {
        size_t o = (size_t)(nc + i) * K_ + kc + tx;
        Thi[o] = __float2half(t[tx][i]);
    }
}

// ============================================================================
// fp16 2-term HMMA GEMM: C = (Ahi+Alo) @ Bhi^T (+bias)
// 96x64x64 tiles, 192 threads (6 warps, 3x2), 2-stage cp.async, 3 CTAs/SM
// ============================================================================
#define NCHUNK   (K_/64)          // 12
#define A_B      (96*128)         // 12KB per A tile (hi or lo)
#define B_B      (64*128)         // 8KB  B tile
#define STAGE_B  (2*A_B + B_B)    // 32KB per stage
#define GEMM_SMEM (2*STAGE_B)     // 64KB

template <int HALF_OUT>
__global__ __launch_bounds__(192, 3)
void hmma_gemm_kernel(const __half* __restrict__ Ahi,
                      const __half* __restrict__ Alo,
                      const __half* __restrict__ Bh,
                      const float* __restrict__ bias,
                      void* __restrict__ CoutV,
                      int Ncols, int Mrows)
{
    extern __shared__ unsigned char smem[];
    const uint32_t s_base = smem_u32(smem);

    const int tid   = threadIdx.x;
    const int wid   = tid >> 5;          // 0..5
    const int lane  = tid & 31;
    const int m0    = blockIdx.y * 96;
    const int n0    = blockIdx.x * 64;
    const int wm    = (wid >> 1) * 32;   // 0/32/64
    const int wn    = (wid & 1) * 32;    // 0/32

    const int lr = tid >> 3;   // 0..23
    const int lc = tid & 7;
    auto load_stage = [&](int st, int kc) {
        const uint32_t sb = s_base + st * STAGE_B;
        const int k0 = kc * 64 + lc * 8;
#pragma unroll
        for (int i = 0; i < 4; i++) {
            const int row = lr + i * 24;   // 0..95
            const uint32_t so = row * 128 + ((lc ^ (row & 7)) << 4);
            const size_t ga = (size_t)(m0 + row) * K_ + k0;
            cp_async16(sb + so,        Ahi + ga);
            cp_async16(sb + A_B + so,  Alo + ga);
        }
#pragma unroll
        for (int i = 0; i < 3; i++) {
            const int row = lr + i * 24;   // 0..71
            if (row < 64) {
                const uint32_t so = row * 128 + ((lc ^ (row & 7)) << 4);
                const size_t gb = (size_t)(n0 + row) * K_ + k0;
                cp_async16(sb + 2*A_B + so, Bh + gb);
            }
        }
    };

    float acc[2][4][4];
#pragma unroll
    for (int i = 0; i < 2; i++)
#pragma unroll
        for (int j = 0; j < 4; j++)
#pragma unroll
            for (int v = 0; v < 4; v++) acc[i][j][v] = 0.f;

    load_stage(0, 0); cp_commit();

    const int a_row = (lane & 15);
    const int a_chi = (lane >> 4);
    const int b_row = (lane & 7) + ((lane >> 4) << 3);
    const int b_chi = (lane >> 3) & 1;

    for (int kc = 0; kc < NCHUNK; kc++) {
        if (kc + 1 < NCHUNK) {
            load_stage((kc + 1) & 1, kc + 1);
            cp_commit();
            cp_wait<1>();
        } else {
            cp_wait<0>();
        }
        __syncthreads();

        const uint32_t sb   = s_base + (kc & 1) * STAGE_B;
        const uint32_t sAhi = sb;
        const uint32_t sAlo = sb + A_B;
        const uint32_t sBh  = sb + 2*A_B;

#pragma unroll
        for (int s = 0; s < 4; s++) {
            uint32_t fah[2][4], fal[2][4];
#pragma unroll
            for (int mi = 0; mi < 2; mi++) {
                const int row = wm + mi * 16 + a_row;
                const int ch  = (2 * s + a_chi) ^ (row & 7);
                const uint32_t off = row * 128 + (ch << 4);
                ldmatrix_x4(fah[mi][0], fah[mi][1], fah[mi][2], fah[mi][3], sAhi + off);
                ldmatrix_x4(fal[mi][0], fal[mi][1], fal[mi][2], fal[mi][3], sAlo + off);
            }
            uint32_t fbh[2][4];
#pragma unroll
            for (int ng = 0; ng < 2; ng++) {
                const int row = wn + ng * 16 + b_row;
                const int ch  = (2 * s + b_chi) ^ (row & 7);
                const uint32_t off = row * 128 + (ch << 4);
                ldmatrix_x4(fbh[ng][0], fbh[ng][1], fbh[ng][2], fbh[ng][3], sBh + off);
            }
#pragma unroll
            for (int mi = 0; mi < 2; mi++) {
#pragma unroll
                for (int ng = 0; ng < 2; ng++) {
#pragma unroll
                    for (int hh = 0; hh < 2; hh++) {
                        float* c = acc[mi][ng * 2 + hh];
                        const uint32_t b0 = fbh[ng][hh * 2], b1 = fbh[ng][hh * 2 + 1];
                        mma_fp16(c, fah[mi], b0, b1);
                        mma_fp16(c, fal[mi], b0, b1);
                    }
                }
            }
        }
        __syncthreads();
    }

#pragma unroll
    for (int ni = 0; ni < 4; ni++) {
        const int col = n0 + wn + ni * 8 + (lane & 3) * 2;
        if (HALF_OUT) {
            __half* Cout = (__half*)CoutV;
#pragma unroll
            for (int mi = 0; mi < 2; mi++) {
                const int r0 = m0 + wm + mi * 16 + (lane >> 2);
                if (r0 < Mrows) {
                    __half2 v; v.x = __float2half(acc[mi][ni][0]); v.y = __float2half(acc[mi][ni][1]);
                    *(__half2*)(Cout + (size_t)r0 * Ncols + col) = v;
                }
                const int r1 = r0 + 8;
                if (r1 < Mrows) {
                    __half2 v; v.x = __float2half(acc[mi][ni][2]); v.y = __float2half(acc[mi][ni][3]);
                    *(__half2*)(Cout + (size_t)r1 * Ncols + col) = v;
                }
            }
        } else {
            float* Cout = (float*)CoutV;
            const float bx = bias ? bias[col]     : 0.f;
            const float by = bias ? bias[col + 1] : 0.f;
#pragma unroll
            for (int mi = 0; mi < 2; mi++) {
                const int r0 = m0 + wm + mi * 16 + (lane >> 2);
                if (r0 < Mrows) {
                    float2 v = make_float2(acc[mi][ni][0] + bx, acc[mi][ni][1] + by);
                    *(float2*)(Cout + (size_t)r0 * Ncols + col) = v;
                }
                const int r1 = r0 + 8;
                if (r1 < Mrows) {
                    float2 v = make_float2(acc[mi][ni][2] + bx, acc[mi][ni][3] + by);
                    *(float2*)(Cout + (size_t)r1 * Ncols + col) = v;
                }
            }
        }
    }
}

// ============================================================================
// merged attention kernel (R12 structure — best measured: single-pass cp.async
// fill, fp16 smem K+V, pack smem for probs)
// ============================================================================
#define MAXNK     169
#define KSTRH     72                 // halves per K/V row (144B)
#define NLOCALBLK (B_*H_*GRID_)      // 9216
#define SQ_H      (24*64)            // 1536 halves (3072B)
#define SKV_H     (MAXNK*KSTRH)      // 12168 halves (24336B)
#define ATT_SMEM  (SQ_H*2 + 2*SKV_H*2 + 24*64*8)   // 64,032 B

__global__ __launch_bounds__(256, 3)
void attn_kernel()
{
    extern __shared__ unsigned char smraw[];

    const int tid  = threadIdx.x;
    const int lane = tid & 31;
    const int warp = tid >> 5;
    const int blk  = blockIdx.x;

    if (blk < NLOCALBLK) {
        __half* sQ  = (__half*)smraw;                       // [24][64]
        __half* sK  = sQ + SQ_H;                            // [169][72]
        __half* sV  = sK + SKV_H;                           // [169][72]
        float2* pack = (float2*)(smraw + SQ_H*2 + 2*SKV_H*2); // [24][64]
        const uint32_t aQ = smem_u32(sQ);
        const uint32_t aK = smem_u32(sK);
        const uint32_t aV = smem_u32(sV);

        const int r = blk % GRID_;
        const int h = (blk / GRID_) % H_;
        const int b = blk / (GRID_ * H_);

        const int r0   = (r - RAD_ < 0) ? 0 : r - RAD_;
        const int r1   = (r + RAD_ > GRID_ - 1) ? GRID_ - 1 : r + RAD_;
        const int span = r1 - r0 + 1;
        const int nk   = span * GRID_ + 1;

        const size_t krow0 = (size_t)b * N_ * (3 * C_);
        const int koff = C_ + h * D_;
        const int voff = 2 * C_ + h * D_;
        const size_t qbase = ((size_t)b * N_ + 1 + r * GRID_) * (3 * C_) + h * D_;

        // ---- single async fill: queries + K band + V band ----
        for (int i = tid; i < 24 * 8; i += 256) {
            const int c    = i >> 3;
            const int part = i & 7;
            cp_async16(aQ + (uint32_t)(c * 64 + part * 8) * 2,
                       g_QKV + qbase + (size_t)c * (3 * C_) + part * 8);
        }
        for (int i = tid; i < nk * 8; i += 256) {
            const int slot = i >> 3;
            const int part = i & 7;
            const int gkey = (slot == 0) ? 0
                           : (1 + (r0 + (slot - 1) / GRID_) * GRID_ + (slot - 1) % GRID_);
            const __half* gp = g_QKV + krow0 + (size_t)gkey * (3 * C_);
            const uint32_t so = (uint32_t)(slot * KSTRH + part * 8) * 2;
            cp_async16(aK + so, gp + koff + part * 8);
            cp_async16(aV + so, gp + voff + part * 8);
        }
        cp_commit();
        cp_wait<0>();
        __syncthreads();

        // ---- QK + softmax ----
        for (int c = warp; c < GRID_; c += 8) {
            const int c0 = (c - RAD_ < 0) ? 0 : c - RAD_;
            const int c1 = (c + RAD_ > GRID_ - 1) ? GRID_ - 1 : c + RAD_;
            const int cw = c1 - c0 + 1;
            const int cnt = 1 + span * cw;

            int slot0 = 0, slot1 = 0;
            if (lane > 0 && lane < cnt) {
                const int j = lane - 1;
                slot0 = 1 + (j / cw) * GRID_ + (c0 + j % cw);
            }
            if (lane + 32 < cnt) {
                const int j = lane + 31;
                slot1 = 1 + (j / cw) * GRID_ + (c0 + j % cw);
            }
            const __half* qrow = sQ + c * 64;
            const __half* k0r  = sK + slot0 * KSTRH;
            const __half* k1r  = sK + slot1 * KSTRH;
            float acc0 = 0.f, acc1 = 0.f;
#pragma unroll
            for (int i = 0; i < 8; i++) {
                const uint4 qv = *(const uint4*)(qrow + i * 8);
                const uint4 k0 = *(const uint4*)(k0r + i * 8);
                const uint4 k1 = *(const uint4*)(k1r + i * 8);
                const __half2* qh = (const __half2*)&qv;
                const __half2* kh0 = (const __half2*)&k0;
                const __half2* kh1 = (const __half2*)&k1;
#pragma unroll
                for (int w = 0; w < 4; w++) {
                    const float2 qf = __half22float2(qh[w]);
                    const float2 f0 = __half22float2(kh0[w]);
                    const float2 f1 = __half22float2(kh1[w]);
                    acc0 = fmaf(qf.x, f0.x, acc0);
                    acc0 = fmaf(qf.y, f0.y, acc0);
                    acc1 = fmaf(qf.x, f1.x, acc1);
                    acc1 = fmaf(qf.y, f1.y, acc1);
                }
            }
            float s0 = (lane < cnt)      ? acc0 * 0.125f : -1e30f;
            float s1 = (lane + 32 < cnt) ? acc1 * 0.125f : -1e30f;

            float mx = fmaxf(s0, s1);
#pragma unroll
            for (int off = 16; off; off >>= 1)
                mx = fmaxf(mx, __shfl_xor_sync(0xffffffffu, mx, off));
            const float e0 = __expf(s0 - mx);
            const float e1 = __expf(s1 - mx);
            float sum = e0 + e1;
#pragma unroll
            for (int off = 16; off; off >>= 1)
                sum += __shfl_xor_sync(0xffffffffu, sum, off);
            const float inv = 1.0f / sum;

            pack[c * 64 + lane]      = make_float2(e0 * inv, __int_as_float(slot0));
            pack[c * 64 + lane + 32] = make_float2(e1 * inv, __int_as_float(slot1));
        }
        __syncwarp();

        // ---- AV ----
        for (int c = warp; c < GRID_; c += 8) {
            const int n = 1 + r * GRID_ + c;
            const size_t rowm = (size_t)b * N_ + n;
            const int c0 = (c - RAD_ < 0) ? 0 : c - RAD_;
            const int c1 = (c + RAD_ > GRID_ - 1) ? GRID_ - 1 : c + RAD_;
            const int cw = c1 - c0 + 1;
            const int cnt = 1 + span * cw;

            const float2* wp = pack + c * 64;
            float a0 = 0.f, a1 = 0.f;     // dims 2*lane, 2*lane+1
            for (int i = 0; i < cnt; i++) {
                const float2 ps = wp[i];
                const int slot = __float_as_int(ps.y);
                const __half2 vh = *(const __half2*)(sV + slot * KSTRH + 2 * lane);
                const float2 vf = __half22float2(vh);
                a0 = fmaf(ps.x, vf.x, a0);
                a1 = fmaf(ps.x, vf.y, a1);
            }

            const size_t o = rowm * C_ + h * D_ + 2 * lane;
            const __half h0 = __float2half(a0);
            const __half h1 = __float2half(a1);
            __half2 hp; hp.x = h0; hp.y = h1;
            __half2 lp;
            lp.x = __float2half(a0 - __half2float(h0));
            lp.y = __float2half(a1 - __half2float(h1));
            *(__half2*)(g_Ohi + o) = hp;
            *(__half2*)(g_Olo + o) = lp;
        }
    } else {
        // ---------------- CLS CTA ----------------
        float* sm     = (float*)smraw;
        float* scores = sm;                 // [577] (+pad)
        float* partA  = sm + 640;           // [8][64]
        float* red    = sm + 640 + 8 * 64;  // [8]

        const int w2 = blk - NLOCALBLK;
        const int b  = w2 / H_;
        const int h  = w2 % H_;

        const size_t rowm = (size_t)b * N_;   // n = 0
        const __half* qp = g_QKV + rowm * (3 * C_) + h * D_;
        const float q0 = __half2float(qp[lane]);
        const float q1 = __half2float(qp[lane + 32]);

        const size_t krow0 = (size_t)b * N_ * (3 * C_);
        const int koff = C_ + h * D_;
        const int voff = 2 * C_ + h * D_;

        for (int j = warp; j < N_; j += 8) {
            const __half* kp = g_QKV + krow0 + (size_t)j * (3 * C_) + koff;
            float s = q0 * __half2float(kp[lane]) + q1 * __half2float(kp[lane + 32]);
#pragma unroll
            for (int off = 16; off; off >>= 1)
                s += __shfl_xor_sync(0xffffffffu, s, off);
            if (lane == 0) scores[j] = s * 0.125f;
        }
        __syncthreads();

        float mx = -1e30f;
        for (int i = tid; i < N_; i += 256) mx = fmaxf(mx, scores[i]);
#pragma unroll
        for (int off = 16; off; off >>= 1)
            mx = fmaxf(mx, __shfl_xor_sync(0xffffffffu, mx, off));
        if (lane == 0) red[warp] = mx;
        __syncthreads();
        mx = red[0];
#pragma unroll
        for (int w = 1; w < 8; w++) mx = fmaxf(mx, red[w]);
        __syncthreads();

        float lsum = 0.f;
        for (int i = tid; i < N_; i += 256) {
            float e = __expf(scores[i] - mx);
            scores[i] = e;
            lsum += e;
        }
#pragma unroll
        for (int off = 16; off; off >>= 1)
            lsum += __shfl_xor_sync(0xffffffffu, lsum, off);
        if (lane == 0) red[warp] = lsum;
        __syncthreads();
        float sum = 0.f;
#pragma unroll
        for (int w = 0; w < 8; w++) sum += red[w];
        const float inv = 1.0f / sum;

        float a0 = 0.f, a1 = 0.f;
        for (int j = warp; j < N_; j += 8) {
            const float p = scores[j];
            const __half* vp = g_QKV + krow0 + (size_t)j * (3 * C_) + voff;
            a0 = fmaf(p, __half2float(vp[lane]),      a0);
            a1 = fmaf(p, __half2float(vp[lane + 32]), a1);
        }
        partA[warp * 64 + lane]      = a0;
        partA[warp * 64 + lane + 32] = a1;
        __syncthreads();

        if (warp == 0) {
            float t0 = 0.f, t1 = 0.f;
#pragma unroll
            for (int w = 0; w < 8; w++) {
                t0 += partA[w * 64 + lane];
                t1 += partA[w * 64 + lane + 32];
            }
            t0 *= inv; t1 *= inv;
            const size_t o = rowm * C_ + h * D_;
            const __half h0 = __float2half(t0);
            const __half h1 = __float2half(t1);
            g_Ohi[o + lane]      = h0;
            g_Olo[o + lane]      = __float2half(t0 - __half2float(h0));
            g_Ohi[o + lane + 32] = h1;
            g_Olo[o + lane + 32] = __float2half(t1 - __half2float(h1));
        }
    }
}

// ============================================================================
// launch
// ============================================================================
extern "C" void kernel_launch(void* const* d_in, const int* in_sizes, int n_in,
                              void* d_out, int out_size)
{
    const float* x     = (const float*)d_in[0];
    const float* Wqkv  = (const float*)d_in[1];
    const float* Wproj = (const float*)d_in[2];
    const float* bproj = (const float*)d_in[3];
    float* out = (float*)d_out;

    cudaFuncSetAttribute(hmma_gemm_kernel<0>,
                         cudaFuncAttributeMaxDynamicSharedMemorySize, GEMM_SMEM);
    cudaFuncSetAttribute(hmma_gemm_kernel<1>,
                         cudaFuncAttributeMaxDynamicSharedMemorySize, GEMM_SMEM);
    cudaFuncSetAttribute(attn_kernel,
                         cudaFuncAttributeMaxDynamicSharedMemorySize, ATT_SMEM);

    __half *xhi, *xlo, *whi, *phi, *ohi, *olo, *qkv;
    cudaGetSymbolAddress((void**)&xhi, g_xhi);
    cudaGetSymbolAddress((void**)&xlo, g_xlo);
    cudaGetSymbolAddress((void**)&whi, g_Whi);
    cudaGetSymbolAddress((void**)&phi, g_Phi);
    cudaGetSymbolAddress((void**)&ohi, g_Ohi);
    cudaGetSymbolAddress((void**)&olo, g_Olo);
    cudaGetSymbolAddress((void**)&qkv, g_QKV);

    // 0) conversions
    {
        size_t total = (size_t)MPAD_ * K_;
        conv_x_kernel<<<(unsigned)((total + 255) / 256), 256>>>(x);
        conv_wT_kernel<<<dim3(3 * C_ / 32, K_ / 32), 256>>>(Wqkv, whi, 3 * C_);
        conv_wT_kernel<<<dim3(C_ / 32, K_ / 32), 256>>>(Wproj, phi, C_);
    }

    // 1) QKV GEMM: [M,768] @ [2304,768]^T -> g_QKV (fp16)
    hmma_gemm_kernel<1><<<dim3(3 * C_ / 64, MTG_), 192, GEMM_SMEM>>>(
        xhi, xlo, whi, nullptr, qkv, 3 * C_, M_);

    // 2) attention (local + CLS in one launch)
    attn_kernel<<<NLOCALBLK + B_ * H_, 256, ATT_SMEM>>>();

    // 3) proj GEMM: [M,768] @ [768,768]^T + bias -> out (fp32)
    hmma_gemm_kernel<0><<<dim3(C_ / 64, MTG_), 192, GEMM_SMEM>>>(
        ohi, olo, phi, bproj, out, C_, M_);
}

// round 15
// speedup vs baseline: 1.1296x; 1.0438x over previous
#include <cuda_runtime.h>
#include <cuda_fp16.h>
#include <cstdint>
#include <math.h>

// ---------------- problem constants ----------------
#define B_    32
#define N_    577
#define C_    768
#define H_    12
#define D_    64
#define GRID_ 24
#define RAD_  3
#define K_    768
#define M_    (B_*N_)      // 18464
#define MT_   145          // ceil(M/128)
#define MPAD_ (MT_*128)    // 18560

// ---------------- device-global scratch ----------------
__device__ __half  g_xhi[MPAD_*K_];
__device__ __half  g_xlo[MPAD_*K_];
__device__ __half  g_Whi[3*C_*K_];   // Wqkv^T  [2304,768] fp16
__device__ __half  g_Phi[C_*K_];     // Wproj^T [768,768]  fp16
__device__ __half  g_QKV[(size_t)M_*3*C_];      // [m, 2304] fp16
__device__ __half  g_Ohi[MPAD_*C_];
__device__ __half  g_Olo[MPAD_*C_];

// ---------------- PTX helpers ----------------
__device__ __forceinline__ uint32_t smem_u32(const void* p) {
    uint32_t a;
    asm("{ .reg .u64 t; cvta.to.shared.u64 t, %1; cvt.u32.u64 %0, t; }" : "=r"(a) : "l"(p));
    return a;
}
__device__ __forceinline__ void cp_async16(uint32_t dst, const void* src) {
    asm volatile("cp.async.cg.shared.global [%0], [%1], 16;" :: "r"(dst), "l"(src));
}
__device__ __forceinline__ void cp_commit() {
    asm volatile("cp.async.commit_group;");
}
template <int NN>
__device__ __forceinline__ void cp_wait() {
    asm volatile("cp.async.wait_group %0;" :: "n"(NN));
}
__device__ __forceinline__ void ldmatrix_x4(uint32_t& r0, uint32_t& r1,
                                            uint32_t& r2, uint32_t& r3, uint32_t addr) {
    asm volatile("ldmatrix.sync.aligned.m8n8.x4.shared.b16 {%0,%1,%2,%3}, [%4];"
                 : "=r"(r0), "=r"(r1), "=r"(r2), "=r"(r3) : "r"(addr));
}
__device__ __forceinline__ void mma_fp16(float* c, const uint32_t* a,
                                         uint32_t b0, uint32_t b1) {
    asm volatile(
        "mma.sync.aligned.m16n8k16.row.col.f32.f16.f16.f32 "
        "{%0,%1,%2,%3}, {%4,%5,%6,%7}, {%8,%9}, {%0,%1,%2,%3};"
        : "+f"(c[0]), "+f"(c[1]), "+f"(c[2]), "+f"(c[3])
        : "r"(a[0]), "r"(a[1]), "r"(a[2]), "r"(a[3]), "r"(b0), "r"(b1));
}

// ============================================================================
// conversion kernels
// ============================================================================
__global__ void conv_x_kernel(const float* __restrict__ x) {
    size_t idx = (size_t)blockIdx.x * 256 + threadIdx.x;
    if (idx >= (size_t)MPAD_ * K_) return;
    size_t m = idx / K_;
    if (m < M_) {
        float a = x[idx];
        __half hi = __float2half(a);
        __half lo = __float2half(a - __half2float(hi));
        g_xhi[idx] = hi;
        g_xlo[idx] = lo;
    } else {
        g_xhi[idx] = __float2half(0.f);
        g_xlo[idx] = __float2half(0.f);
        g_Ohi[idx] = __float2half(0.f);
        g_Olo[idx] = __float2half(0.f);
    }
}

__global__ void conv_wT_kernel(const float* __restrict__ W,
                               __half* __restrict__ Thi, int Ncols) {
    __shared__ float t[32][33];
    const int kc = blockIdx.y * 32;
    const int nc = blockIdx.x * 32;
    const int tx = threadIdx.x & 31;
    const int ty = threadIdx.x >> 5;
    for (int i = ty; i < 32; i += 8)
        t[i][tx] = W[(size_t)(kc + i) * Ncols + nc + tx];
    __syncthreads();
    for (int i = ty; i < 32; i += 8) {
        size_t o = (size_t)(nc + i) * K_ + kc + tx;
        Thi[o] = __float2half(t[tx][i]);
    }
}

// ============================================================================
// fp16 2-term HMMA GEMM: C = (Ahi+Alo) @ Bhi^T (+bias)
// 128x64x64 tiles, 4 warps (4x1), warp tile 32x64, 2-stage cp.async, 2 CTAs/SM
// A read by exactly one warp (amp x1), B by 4 -> 152 B/output smem traffic
// ============================================================================
#define NCHUNK   (K_/64)          // 12
#define A_B      (128*128)        // 16KB per A tile (hi or lo)
#define B_B      (64*128)         // 8KB  B tile
#define STAGE_B  (2*A_B + B_B)    // 40KB
#define GEMM_SMEM (2*STAGE_B)     // 80KB

template <int HALF_OUT>
__global__ __launch_bounds__(128, 2)
void hmma_gemm_kernel(const __half* __restrict__ Ahi,
                      const __half* __restrict__ Alo,
                      const __half* __restrict__ Bh,
                      const float* __restrict__ bias,
                      void* __restrict__ CoutV,
                      int Ncols, int Mrows)
{
    extern __shared__ unsigned char smem[];
    const uint32_t s_base = smem_u32(smem);

    const int tid   = threadIdx.x;
    const int wid   = tid >> 5;          // 0..3
    const int lane  = tid & 31;
    const int m0    = blockIdx.y * 128;
    const int n0    = blockIdx.x * 64;
    const int wm    = wid * 32;          // 0/32/64/96

    // loader: 40KB = 2560 x 16B; 128 threads x 20
    const int lr = tid >> 3;   // 0..15
    const int lc = tid & 7;
    auto load_stage = [&](int st, int kc) {
        const uint32_t sb = s_base + st * STAGE_B;
        const int k0 = kc * 64 + lc * 8;
#pragma unroll
        for (int i = 0; i < 8; i++) {
            const int row = lr + i * 16;   // 0..127
            const uint32_t so = row * 128 + ((lc ^ (row & 7)) << 4);
            const size_t ga = (size_t)(m0 + row) * K_ + k0;
            cp_async16(sb + so,        Ahi + ga);
            cp_async16(sb + A_B + so,  Alo + ga);
        }
#pragma unroll
        for (int i = 0; i < 4; i++) {
            const int row = lr + i * 16;   // 0..63
            const uint32_t so = row * 128 + ((lc ^ (row & 7)) << 4);
            const size_t gb = (size_t)(n0 + row) * K_ + k0;
            cp_async16(sb + 2*A_B + so, Bh + gb);
        }
    };

    float acc[2][8][4];
#pragma unroll
    for (int i = 0; i < 2; i++)
#pragma unroll
        for (int j = 0; j < 8; j++)
#pragma unroll
            for (int v = 0; v < 4; v++) acc[i][j][v] = 0.f;

    load_stage(0, 0); cp_commit();

    const int a_row = (lane & 15);
    const int a_chi = (lane >> 4);
    const int b_row = (lane & 7) + ((lane >> 4) << 3);
    const int b_chi = (lane >> 3) & 1;

    for (int kc = 0; kc < NCHUNK; kc++) {
        if (kc + 1 < NCHUNK) {
            load_stage((kc + 1) & 1, kc + 1);
            cp_commit();
            cp_wait<1>();
        } else {
            cp_wait<0>();
        }
        __syncthreads();

        const uint32_t sb   = s_base + (kc & 1) * STAGE_B;
        const uint32_t sAhi = sb;
        const uint32_t sAlo = sb + A_B;
        const uint32_t sBh  = sb + 2*A_B;

#pragma unroll
        for (int s = 0; s < 4; s++) {
            uint32_t fah[2][4], fal[2][4];
#pragma unroll
            for (int mi = 0; mi < 2; mi++) {
                const int row = wm + mi * 16 + a_row;
                const int ch  = (2 * s + a_chi) ^ (row & 7);
                const uint32_t off = row * 128 + (ch << 4);
                ldmatrix_x4(fah[mi][0], fah[mi][1], fah[mi][2], fah[mi][3], sAhi + off);
                ldmatrix_x4(fal[mi][0], fal[mi][1], fal[mi][2], fal[mi][3], sAlo + off);
            }
            uint32_t fbh[4][4];
#pragma unroll
            for (int ng = 0; ng < 4; ng++) {
                const int row = ng * 16 + b_row;
                const int ch  = (2 * s + b_chi) ^ (row & 7);
                const uint32_t off = row * 128 + (ch << 4);
                ldmatrix_x4(fbh[ng][0], fbh[ng][1], fbh[ng][2], fbh[ng][3], sBh + off);
            }
#pragma unroll
            for (int mi = 0; mi < 2; mi++) {
#pragma unroll
                for (int ng = 0; ng < 4; ng++) {
#pragma unroll
                    for (int hh = 0; hh < 2; hh++) {
                        float* c = acc[mi][ng * 2 + hh];
                        const uint32_t b0 = fbh[ng][hh * 2], b1 = fbh[ng][hh * 2 + 1];
                        mma_fp16(c, fah[mi], b0, b1);
                        mma_fp16(c, fal[mi], b0, b1);
                    }
                }
            }
        }
        __syncthreads();
    }

#pragma unroll
    for (int ni = 0; ni < 8; ni++) {
        const int col = n0 + (ni >> 1) * 16 + (ni & 1) * 8 + (lane & 3) * 2;
        if (HALF_OUT) {
            __half* Cout = (__half*)CoutV;
#pragma unroll
            for (int mi = 0; mi < 2; mi++) {
                const int r0 = m0 + wm + mi * 16 + (lane >> 2);
                if (r0 < Mrows) {
                    __half2 v; v.x = __float2half(acc[mi][ni][0]); v.y = __float2half(acc[mi][ni][1]);
                    *(__half2*)(Cout + (size_t)r0 * Ncols + col) = v;
                }
                const int r1 = r0 + 8;
                if (r1 < Mrows) {
                    __half2 v; v.x = __float2half(acc[mi][ni][2]); v.y = __float2half(acc[mi][ni][3]);
                    *(__half2*)(Cout + (size_t)r1 * Ncols + col) = v;
                }
            }
        } else {
            float* Cout = (float*)CoutV;
            const float bx = bias ? bias[col]     : 0.f;
            const float by = bias ? bias[col + 1] : 0.f;
#pragma unroll
            for (int mi = 0; mi < 2; mi++) {
                const int r0 = m0 + wm + mi * 16 + (lane >> 2);
                if (r0 < Mrows) {
                    float2 v = make_float2(acc[mi][ni][0] + bx, acc[mi][ni][1] + by);
                    *(float2*)(Cout + (size_t)r0 * Ncols + col) = v;
                }
                const int r1 = r0 + 8;
                if (r1 < Mrows) {
                    float2 v = make_float2(acc[mi][ni][2] + bx, acc[mi][ni][3] + by);
                    *(float2*)(Cout + (size_t)r1 * Ncols + col) = v;
                }
            }
        }
    }
}

// ============================================================================
// merged attention kernel (R12 structure — best measured)
// ============================================================================
#define MAXNK     169
#define KSTRH     72
#define NLOCALBLK (B_*H_*GRID_)      // 9216
#define SQ_H      (24*64)
#define SKV_H     (MAXNK*KSTRH)
#define ATT_SMEM  (SQ_H*2 + 2*SKV_H*2 + 24*64*8)   // 64,032 B

__global__ __launch_bounds__(256, 3)
void attn_kernel()
{
    extern __shared__ unsigned char smraw[];

    const int tid  = threadIdx.x;
    const int lane = tid & 31;
    const int warp = tid >> 5;
    const int blk  = blockIdx.x;

    if (blk < NLOCALBLK) {
        __half* sQ  = (__half*)smraw;                       // [24][64]
        __half* sK  = sQ + SQ_H;                            // [169][72]
        __half* sV  = sK + SKV_H;                           // [169][72]
        float2* pack = (float2*)(smraw + SQ_H*2 + 2*SKV_H*2); // [24][64]
        const uint32_t aQ = smem_u32(sQ);
        const uint32_t aK = smem_u32(sK);
        const uint32_t aV = smem_u32(sV);

        const int r = blk % GRID_;
        const int h = (blk / GRID_) % H_;
        const int b = blk / (GRID_ * H_);

        const int r0   = (r - RAD_ < 0) ? 0 : r - RAD_;
        const int r1   = (r + RAD_ > GRID_ - 1) ? GRID_ - 1 : r + RAD_;
        const int span = r1 - r0 + 1;
        const int nk   = span * GRID_ + 1;

        const size_t krow0 = (size_t)b * N_ * (3 * C_);
        const int koff = C_ + h * D_;
        const int voff = 2 * C_ + h * D_;
        const size_t qbase = ((size_t)b * N_ + 1 + r * GRID_) * (3 * C_) + h * D_;

        for (int i = tid; i < 24 * 8; i += 256) {
            const int c    = i >> 3;
            const int part = i & 7;
            cp_async16(aQ + (uint32_t)(c * 64 + part * 8) * 2,
                       g_QKV + qbase + (size_t)c * (3 * C_) + part * 8);
        }
        for (int i = tid; i < nk * 8; i += 256) {
            const int slot = i >> 3;
            const int part = i & 7;
            const int gkey = (slot == 0) ? 0
                           : (1 + (r0 + (slot - 1) / GRID_) * GRID_ + (slot - 1) % GRID_);
            const __half* gp = g_QKV + krow0 + (size_t)gkey * (3 * C_);
            const uint32_t so = (uint32_t)(slot * KSTRH + part * 8) * 2;
            cp_async16(aK + so, gp + koff + part * 8);
            cp_async16(aV + so, gp + voff + part * 8);
        }
        cp_commit();
        cp_wait<0>();
        __syncthreads();

        for (int c = warp; c < GRID_; c += 8) {
            const int c0 = (c - RAD_ < 0) ? 0 : c - RAD_;
            const int c1 = (c + RAD_ > GRID_ - 1) ? GRID_ - 1 : c + RAD_;
            const int cw = c1 - c0 + 1;
            const int cnt = 1 + span * cw;

            int slot0 = 0, slot1 = 0;
            if (lane > 0 && lane < cnt) {
                const int j = lane - 1;
                slot0 = 1 + (j / cw) * GRID_ + (c0 + j % cw);
            }
            if (lane + 32 < cnt) {
                const int j = lane + 31;
                slot1 = 1 + (j / cw) * GRID_ + (c0 + j % cw);
            }
            const __half* qrow = sQ + c * 64;
            const __half* k0r  = sK + slot0 * KSTRH;
            const __half* k1r  = sK + slot1 * KSTRH;
            float acc0 = 0.f, acc1 = 0.f;
#pragma unroll
            for (int i = 0; i < 8; i++) {
                const uint4 qv = *(const uint4*)(qrow + i * 8);
                const uint4 k0 = *(const uint4*)(k0r + i * 8);
                const uint4 k1 = *(const uint4*)(k1r + i * 8);
                const __half2* qh = (const __half2*)&qv;
                const __half2* kh0 = (const __half2*)&k0;
                const __half2* kh1 = (const __half2*)&k1;
#pragma unroll
                for (int w = 0; w < 4; w++) {
                    const float2 qf = __half22float2(qh[w]);
                    const float2 f0 = __half22float2(kh0[w]);
                    const float2 f1 = __half22float2(kh1[w]);
                    acc0 = fmaf(qf.x, f0.x, acc0);
                    acc0 = fmaf(qf.y, f0.y, acc0);
                    acc1 = fmaf(qf.x, f1.x, acc1);
                    acc1 = fmaf(qf.y, f1.y, acc1);
                }
            }
            float s0 = (lane < cnt)      ? acc0 * 0.125f : -1e30f;
            float s1 = (lane + 32 < cnt) ? acc1 * 0.125f : -1e30f;

            float mx = fmaxf(s0, s1);
#pragma unroll
            for (int off = 16; off; off >>= 1)
                mx = fmaxf(mx, __shfl_xor_sync(0xffffffffu, mx, off));
            const float e0 = __expf(s0 - mx);
            const float e1 = __expf(s1 - mx);
            float sum = e0 + e1;
#pragma unroll
            for (int off = 16; off; off >>= 1)
                sum += __shfl_xor_sync(0xffffffffu, sum, off);
            const float inv = 1.0f / sum;

            pack[c * 64 + lane]      = make_float2(e0 * inv, __int_as_float(slot0));
            pack[c * 64 + lane + 32] = make_float2(e1 * inv, __int_as_float(slot1));
        }
        __syncwarp();

        for (int c = warp; c < GRID_; c += 8) {
            const int n = 1 + r * GRID_ + c;
            const size_t rowm = (size_t)b * N_ + n;
            const int c0 = (c - RAD_ < 0) ? 0 : c - RAD_;
            const int c1 = (c + RAD_ > GRID_ - 1) ? GRID_ - 1 : c + RAD_;
            const int cw = c1 - c0 + 1;
            const int cnt = 1 + span * cw;

            const float2* wp = pack + c * 64;
            float a0 = 0.f, a1 = 0.f;
            for (int i = 0; i < cnt; i++) {
                const float2 ps = wp[i];
                const int slot = __float_as_int(ps.y);
                const __half2 vh = *(const __half2*)(sV + slot * KSTRH + 2 * lane);
                const float2 vf = __half22float2(vh);
                a0 = fmaf(ps.x, vf.x, a0);
                a1 = fmaf(ps.x, vf.y, a1);
            }

            const size_t o = rowm * C_ + h * D_ + 2 * lane;
            const __half h0 = __float2half(a0);
            const __half h1 = __float2half(a1);
            __half2 hp; hp.x = h0; hp.y = h1;
            __half2 lp;
            lp.x = __float2half(a0 - __half2float(h0));
            lp.y = __float2half(a1 - __half2float(h1));
            *(__half2*)(g_Ohi + o) = hp;
            *(__half2*)(g_Olo + o) = lp;
        }
    } else {
        // ---------------- CLS CTA ----------------
        float* sm     = (float*)smraw;
        float* scores = sm;                 // [577] (+pad)
        float* partA  = sm + 640;           // [8][64]
        float* red    = sm + 640 + 8 * 64;  // [8]

        const int w2 = blk - NLOCALBLK;
        const int b  = w2 / H_;
        const int h  = w2 % H_;

        const size_t rowm = (size_t)b * N_;   // n = 0
        const __half* qp = g_QKV + rowm * (3 * C_) + h * D_;
        const float q0 = __half2float(qp[lane]);
        const float q1 = __half2float(qp[lane + 32]);

        const size_t krow0 = (size_t)b * N_ * (3 * C_);
        const int koff = C_ + h * D_;
        const int voff = 2 * C_ + h * D_;

        for (int j = warp; j < N_; j += 8) {
            const __half* kp = g_QKV + krow0 + (size_t)j * (3 * C_) + koff;
            float s = q0 * __half2float(kp[lane]) + q1 * __half2float(kp[lane + 32]);
#pragma unroll
            for (int off = 16; off; off >>= 1)
                s += __shfl_xor_sync(0xffffffffu, s, off);
            if (lane == 0) scores[j] = s * 0.125f;
        }
        __syncthreads();

        float mx = -1e30f;
        for (int i = tid; i < N_; i += 256) mx = fmaxf(mx, scores[i]);
#pragma unroll
        for (int off = 16; off; off >>= 1)
            mx = fmaxf(mx, __shfl_xor_sync(0xffffffffu, mx, off));
        if (lane == 0) red[warp] = mx;
        __syncthreads();
        mx = red[0];
#pragma unroll
        for (int w = 1; w < 8; w++) mx = fmaxf(mx, red[w]);
        __syncthreads();

        float lsum = 0.f;
        for (int i = tid; i < N_; i += 256) {
            float e = __expf(scores[i] - mx);
            scores[i] = e;
            lsum += e;
        }
#pragma unroll
        for (int off = 16; off; off >>= 1)
            lsum += __shfl_xor_sync(0xffffffffu, lsum, off);
        if (lane == 0) red[warp] = lsum;
        __syncthreads();
        float sum = 0.f;
#pragma unroll
        for (int w = 0; w < 8; w++) sum += red[w];
        const float inv = 1.0f / sum;

        float a0 = 0.f, a1 = 0.f;
        for (int j = warp; j < N_; j += 8) {
            const float p = scores[j];
            const __half* vp = g_QKV + krow0 + (size_t)j * (3 * C_) + voff;
            a0 = fmaf(p, __half2float(vp[lane]),      a0);
            a1 = fmaf(p, __half2float(vp[lane + 32]), a1);
        }
        partA[warp * 64 + lane]      = a0;
        partA[warp * 64 + lane + 32] = a1;
        __syncthreads();

        if (warp == 0) {
            float t0 = 0.f, t1 = 0.f;
#pragma unroll
            for (int w = 0; w < 8; w++) {
                t0 += partA[w * 64 + lane];
                t1 += partA[w * 64 + lane + 32];
            }
            t0 *= inv; t1 *= inv;
            const size_t o = rowm * C_ + h * D_;
            const __half h0 = __float2half(t0);
            const __half h1 = __float2half(t1);
            g_Ohi[o + lane]      = h0;
            g_Olo[o + lane]      = __float2half(t0 - __half2float(h0));
            g_Ohi[o + lane + 32] = h1;
            g_Olo[o + lane + 32] = __float2half(t1 - __half2float(h1));
        }
    }
}

// ============================================================================
// launch
// ============================================================================
extern "C" void kernel_launch(void* const* d_in, const int* in_sizes, int n_in,
                              void* d_out, int out_size)
{
    const float* x     = (const float*)d_in[0];
    const float* Wqkv  = (const float*)d_in[1];
    const float* Wproj = (const float*)d_in[2];
    const float* bproj = (const float*)d_in[3];
    float* out = (float*)d_out;

    cudaFuncSetAttribute(hmma_gemm_kernel<0>,
                         cudaFuncAttributeMaxDynamicSharedMemorySize, GEMM_SMEM);
    cudaFuncSetAttribute(hmma_gemm_kernel<1>,
                         cudaFuncAttributeMaxDynamicSharedMemorySize, GEMM_SMEM);
    cudaFuncSetAttribute(attn_kernel,
                         cudaFuncAttributeMaxDynamicSharedMemorySize, ATT_SMEM);

    __half *xhi, *xlo, *whi, *phi, *ohi, *olo, *qkv;
    cudaGetSymbolAddress((void**)&xhi, g_xhi);
    cudaGetSymbolAddress((void**)&xlo, g_xlo);
    cudaGetSymbolAddress((void**)&whi, g_Whi);
    cudaGetSymbolAddress((void**)&phi, g_Phi);
    cudaGetSymbolAddress((void**)&ohi, g_Ohi);
    cudaGetSymbolAddress((void**)&olo, g_Olo);
    cudaGetSymbolAddress((void**)&qkv, g_QKV);

    // 0) conversions
    {
        size_t total = (size_t)MPAD_ * K_;
        conv_x_kernel<<<(unsigned)((total + 255) / 256), 256>>>(x);
        conv_wT_kernel<<<dim3(3 * C_ / 32, K_ / 32), 256>>>(Wqkv, whi, 3 * C_);
        conv_wT_kernel<<<dim3(C_ / 32, K_ / 32), 256>>>(Wproj, phi, C_);
    }

    // 1) QKV GEMM: [M,768] @ [2304,768]^T -> g_QKV (fp16)
    hmma_gemm_kernel<1><<<dim3(3 * C_ / 64, MT_), 128, GEMM_SMEM>>>(
        xhi, xlo, whi, nullptr, qkv, 3 * C_, M_);

    // 2) attention (local + CLS in one launch)
    attn_kernel<<<NLOCALBLK + B_ * H_, 256, ATT_SMEM>>>();

    // 3) proj GEMM: [M,768] @ [768,768]^T + bias -> out (fp32)
    hmma_gemm_kernel<0><<<dim3(C_ / 64, MT_), 128, GEMM_SMEM>>>(
        ohi, olo, phi, bproj, out, C_, M_);
}